// round 3
// baseline (speedup 1.0000x reference)
#include <cuda_runtime.h>
#include <cuda_bf16.h>

// ThermoQuantizer: groupwise abs-mean scale + softmax quantization onto a
// uniform 16-level codebook + lerp.
//
// Math: p_k ∝ G_k R^k with R = 2^(xn*K2), K2 = 2D/T*log2(e), G_k = exp(-c_k^2/T).
// Symmetric codebook => den(R)=Σ G_k R^k is palindromic (deg 15),
// num(R)=Σ G_k c_k R^k is anti-palindromic. Hence
//   den = (R+1) R^7 Q(z),  num = (R-1) R^7 S(z),  z = R + 1/R,
// with Q,S degree-7 polys whose coefficients are derived per block from the
// codebook/temp (synthetic division + Chebyshev-like basis t_m(z)=R^m+R^-m).
//   qxn = (R-1)S(z) / ((R+1)Q(z))      -- 7 packed FMA + 3 MUFU per element.
//
// Mapping: persistent grid-stride; 1 warp = 2 groups (half-warp per group),
// 8 elements/thread, register double-buffered loads for latency hiding.
// All f32 math packed as element-pairs in fma/mul/add.rn.f32x2.

typedef unsigned long long ull;
#define FULL_MASK 0xFFFFFFFFu

__device__ __forceinline__ ull pk2(float lo, float hi) {
    ull r; asm("mov.b64 %0, {%1, %2};" : "=l"(r) : "f"(lo), "f"(hi)); return r;
}
__device__ __forceinline__ void upk2(ull v, float& lo, float& hi) {
    asm("mov.b64 {%0, %1}, %2;" : "=f"(lo), "=f"(hi) : "l"(v));
}
__device__ __forceinline__ ull fma2(ull a, ull b, ull c) {
    ull d; asm("fma.rn.f32x2 %0, %1, %2, %3;" : "=l"(d) : "l"(a), "l"(b), "l"(c)); return d;
}
__device__ __forceinline__ ull mul2(ull a, ull b) {
    ull d; asm("mul.rn.f32x2 %0, %1, %2;" : "=l"(d) : "l"(a), "l"(b)); return d;
}
__device__ __forceinline__ ull add2(ull a, ull b) {
    ull d; asm("add.rn.f32x2 %0, %1, %2;" : "=l"(d) : "l"(a), "l"(b)); return d;
}
__device__ __forceinline__ float ex2f(float a) {
    float r; asm("ex2.approx.ftz.f32 %0, %1;" : "=f"(r) : "f"(a)); return r;
}
__device__ __forceinline__ float rcpf(float a) {
    float r; asm("rcp.approx.ftz.f32 %0, %1;" : "=f"(r) : "f"(a)); return r;
}

__global__ __launch_bounds__(256) void ThermoQuantizer_50122268345057_kernel(
    const float* __restrict__ x,
    const float* __restrict__ cb,
    const float* __restrict__ pp,
    const float* __restrict__ pt,
    float* __restrict__ out,
    int n4)   // total float4 quads
{
    __shared__ ull sCq[8], sCs[8];       // broadcast pairs (q_j,q_j), (s_j,s_j)
    __shared__ float sK2, sPres, sOneMP;

    if (threadIdx.x == 0) {
        const float invT = 1.0f / (pt[0] + 1e-6f);
        float G[16], H[16];
        #pragma unroll
        for (int k = 0; k < 16; ++k) {
            float c = cb[k];
            float g = __expf(-c * c * invT);
            G[k] = g; H[k] = g * c;
        }
        // den = (R+1)*P, num = (R-1)*M  (synthetic division)
        float p[15], m[15];
        p[0] = G[0]; m[0] = -H[0];
        #pragma unroll
        for (int j = 1; j < 15; ++j) { p[j] = G[j] - p[j - 1]; m[j] = m[j - 1] - H[j]; }
        // P/R^7 = p7 + Σ p_{7+t} t_t(z); t_t(z)=R^t+R^-t power-basis table
        float q[8], s[8];
        q[0] = p[7]; s[0] = m[7];
        #pragma unroll
        for (int j = 1; j < 8; ++j) { q[j] = 0.f; s[j] = 0.f; }
        const float T[7][8] = {
            { 0.f, 1.f, 0.f,  0.f, 0.f, 0.f, 0.f, 0.f},   // t1 = z
            {-2.f, 0.f, 1.f,  0.f, 0.f, 0.f, 0.f, 0.f},   // t2 = z^2-2
            { 0.f,-3.f, 0.f,  1.f, 0.f, 0.f, 0.f, 0.f},   // t3
            { 2.f, 0.f,-4.f,  0.f, 1.f, 0.f, 0.f, 0.f},   // t4
            { 0.f, 5.f, 0.f, -5.f, 0.f, 1.f, 0.f, 0.f},   // t5
            {-2.f, 0.f, 9.f,  0.f,-6.f, 0.f, 1.f, 0.f},   // t6
            { 0.f,-7.f, 0.f, 14.f, 0.f,-7.f, 0.f, 1.f}};  // t7
        #pragma unroll
        for (int t = 1; t <= 7; ++t)
            #pragma unroll
            for (int j = 0; j < 8; ++j) {
                q[j] = fmaf(p[7 + t], T[t - 1][j], q[j]);
                s[j] = fmaf(m[7 + t], T[t - 1][j], s[j]);
            }
        #pragma unroll
        for (int j = 0; j < 8; ++j) { sCq[j] = pk2(q[j], q[j]); sCs[j] = pk2(s[j], s[j]); }
        sK2 = 2.0f * (cb[1] - cb[0]) * invT * 1.4426950408889634f;
        sPres = pp[0];
        sOneMP = 1.0f - pp[0];
    }
    __syncthreads();

    const int lane = threadIdx.x & 31;
    const int h = lane >> 4;          // which of the warp's 2 groups
    const int ql = lane & 15;
    const int warpId = blockIdx.x * (blockDim.x >> 5) + (threadIdx.x >> 5);
    const int numWarps = gridDim.x * (blockDim.x >> 5);
    const int numTiles = (n4 + 63) >> 6;     // 64 quads per warp-tile

    const float K2 = sK2, pres = sPres, onemp = sOneMP;
    const ull om2 = pk2(onemp, onemp);
    const ull ONE2 = pk2(1.0f, 1.0f);
    const ull MONE2 = pk2(-1.0f, -1.0f);

    const float4* __restrict__ x4 = reinterpret_cast<const float4*>(x);
    float4* __restrict__ o4 = reinterpret_cast<float4*>(out);

    int tile = warpId;
    if (tile >= numTiles) return;
    int qb = tile * 64 + h * 32 + ql;
    bool vld = qb < n4;                    // groups are whole-or-absent
    float4 a0 = vld ? x4[qb]      : make_float4(0.f, 0.f, 0.f, 0.f);
    float4 a1 = vld ? x4[qb + 16] : make_float4(0.f, 0.f, 0.f, 0.f);

    while (true) {
        // ---- prefetch next tile (hides DRAM latency behind compute) ----
        const int ntile = tile + numWarps;
        float4 b0 = make_float4(0.f, 0.f, 0.f, 0.f), b1 = b0;
        int nqb = 0; bool nvld = false;
        if (ntile < numTiles) {
            nqb = ntile * 64 + h * 32 + ql;
            nvld = nqb < n4;
            if (nvld) { b0 = x4[nqb]; b1 = x4[nqb + 16]; }
        }

        // ---- group abs-mean over this 16-lane half (128 elements) ----
        float ss = (fabsf(a0.x) + fabsf(a0.y)) + (fabsf(a0.z) + fabsf(a0.w))
                 + (fabsf(a1.x) + fabsf(a1.y)) + (fabsf(a1.z) + fabsf(a1.w));
        ss += __shfl_xor_sync(FULL_MASK, ss, 8);
        ss += __shfl_xor_sync(FULL_MASK, ss, 4);
        ss += __shfl_xor_sync(FULL_MASK, ss, 2);
        ss += __shfl_xor_sync(FULL_MASK, ss, 1);
        const float mean_c = fmaxf(ss * (1.0f / 128.0f), 1e-5f);
        const float kk = K2 * rcpf(mean_c);
        const ull kk2 = pk2(kk, kk);
        const float pm = pres * mean_c;
        const ull pm2 = pk2(pm, pm);

        ull xp[4] = { pk2(a0.x, a0.y), pk2(a0.z, a0.w),
                      pk2(a1.x, a1.y), pk2(a1.z, a1.w) };

        // ---- per-pair: R = 2^clamp(x*kk), z = R + 1/R ----
        ull RP[4], zP[4], accQ[4], accS[4];
        const ull cq7 = sCq[7], cs7 = sCs[7];
        #pragma unroll
        for (int pI = 0; pI < 4; ++pI) {
            ull aP = mul2(xp[pI], kk2);
            float alo, ahi; upk2(aP, alo, ahi);
            alo = fminf(fmaxf(alo, -10.0f), 10.0f);   // softmax already pinned here
            ahi = fminf(fmaxf(ahi, -10.0f), 10.0f);
            float r0 = ex2f(alo), r1 = ex2f(ahi);
            float i0 = rcpf(r0),  i1 = rcpf(r1);
            RP[pI] = pk2(r0, r1);
            zP[pI] = add2(RP[pI], pk2(i0, i1));
            accQ[pI] = cq7; accS[pI] = cs7;
        }

        // ---- dual degree-7 Horner, 8 independent packed chains ----
        #pragma unroll
        for (int j = 6; j >= 0; --j) {
            const ull cq = sCq[j], cs = sCs[j];
            #pragma unroll
            for (int pI = 0; pI < 4; ++pI) {
                accQ[pI] = fma2(accQ[pI], zP[pI], cq);
                accS[pI] = fma2(accS[pI], zP[pI], cs);
            }
        }

        // ---- qxn = (R-1)S / ((R+1)Q);  out = (1-p)x + p*mean*qxn ----
        float resv[8];
        #pragma unroll
        for (int pI = 0; pI < 4; ++pI) {
            ull vP = mul2(accQ[pI], add2(RP[pI], ONE2));
            ull uP = mul2(accS[pI], add2(RP[pI], MONE2));
            float v0, v1, u0, u1; upk2(vP, v0, v1); upk2(uP, u0, u1);
            ull rP = pk2(rcpf(v0), rcpf(v1));
            ull qP = mul2(uP, rP);
            ull resP = fma2(pm2, qP, mul2(om2, xp[pI]));
            upk2(resP, resv[2 * pI], resv[2 * pI + 1]);
        }

        if (vld) {
            o4[qb]      = make_float4(resv[0], resv[1], resv[2], resv[3]);
            o4[qb + 16] = make_float4(resv[4], resv[5], resv[6], resv[7]);
        }

        if (ntile >= numTiles) break;
        tile = ntile; qb = nqb; vld = nvld; a0 = b0; a1 = b1;
    }
}

extern "C" void kernel_launch(void* const* d_in, const int* in_sizes, int n_in,
                              void* d_out, int out_size) {
    const float* x  = (const float*)d_in[0];
    const float* cbk = (const float*)d_in[1];
    const float* pr = (const float*)d_in[2];
    const float* tp = (const float*)d_in[3];
    float* out = (float*)d_out;

    const int n4 = out_size / 4;                   // float4 quads
    const int numTiles = (n4 + 63) >> 6;
    int blocks = 152 * 4;                          // persistent: GB300 = 152 SMs
    const int maxBlocks = (numTiles + 7) / 8;      // 8 warps per block
    if (blocks > maxBlocks) blocks = maxBlocks;
    if (blocks < 1) blocks = 1;
    ThermoQuantizer_50122268345057_kernel<<<blocks, 256>>>(x, cbk, pr, tp, out, n4);
}

// round 4
// speedup vs baseline: 1.1351x; 1.1351x over previous
#include <cuda_runtime.h>
#include <cuda_bf16.h>

// ThermoQuantizer: groupwise abs-mean scale + softmax quantization onto a
// uniform 16-level codebook + lerp.
//
// Math: p_k ∝ G_k R^k, R = 2^(xn*K2), K2 = 2D/T*log2(e), G_k = exp(-c_k^2/T).
// Symmetric codebook => den(R) palindromic / num(R) anti-palindromic (deg 15):
//   den = (R+1) R^7 Q(z),  num = (R-1) R^7 S(z),  z = R + 1/R,  Q,S deg 7.
//   qxn = (R-1)S(z) / ((R+1)Q(z))   -- 7 packed FMA + 3 MUFU per element.
//
// Structure: tiny setup kernel (1 block) derives Q,S coefficients once into
// __device__ globals; main kernel is a flat one-tile-per-warp launch
// (1 warp = 2 groups, 8 elems/thread, all math packed in f32x2).

typedef unsigned long long ull;
#define FULL_MASK 0xFFFFFFFFu

__device__ ull   gC[16];      // packed (q_j,q_j) j=0..7 then (s_j,s_j) j=0..7
__device__ float gK2, gPres;

__device__ __forceinline__ ull pk2(float lo, float hi) {
    ull r; asm("mov.b64 %0, {%1, %2};" : "=l"(r) : "f"(lo), "f"(hi)); return r;
}
__device__ __forceinline__ void upk2(ull v, float& lo, float& hi) {
    asm("mov.b64 {%0, %1}, %2;" : "=f"(lo), "=f"(hi) : "l"(v));
}
__device__ __forceinline__ ull fma2(ull a, ull b, ull c) {
    ull d; asm("fma.rn.f32x2 %0, %1, %2, %3;" : "=l"(d) : "l"(a), "l"(b), "l"(c)); return d;
}
__device__ __forceinline__ ull mul2(ull a, ull b) {
    ull d; asm("mul.rn.f32x2 %0, %1, %2;" : "=l"(d) : "l"(a), "l"(b)); return d;
}
__device__ __forceinline__ ull add2(ull a, ull b) {
    ull d; asm("add.rn.f32x2 %0, %1, %2;" : "=l"(d) : "l"(a), "l"(b)); return d;
}
__device__ __forceinline__ float ex2f(float a) {
    float r; asm("ex2.approx.ftz.f32 %0, %1;" : "=f"(r) : "f"(a)); return r;
}
__device__ __forceinline__ float rcpf(float a) {
    float r; asm("rcp.approx.ftz.f32 %0, %1;" : "=f"(r) : "f"(a)); return r;
}

// ---------------- setup kernel: derive Q,S coefficients (runs once) ---------
__global__ void tq_setup_kernel(const float* __restrict__ cb,
                                const float* __restrict__ pp,
                                const float* __restrict__ pt) {
    if (threadIdx.x != 0) return;
    const float invT = 1.0f / (pt[0] + 1e-6f);
    float G[16], H[16];
    #pragma unroll
    for (int k = 0; k < 16; ++k) {
        float c = cb[k];
        float g = __expf(-c * c * invT);
        G[k] = g; H[k] = g * c;
    }
    // den = (R+1)*P, num = (R-1)*M   (synthetic division)
    float p[15], m[15];
    p[0] = G[0]; m[0] = -H[0];
    #pragma unroll
    for (int j = 1; j < 15; ++j) { p[j] = G[j] - p[j - 1]; m[j] = m[j - 1] - H[j]; }
    // P/R^7 = p7 + Σ p_{7+t} t_t(z), t_t(z) = R^t + R^-t, expanded in powers of z
    float q[8], s[8];
    q[0] = p[7]; s[0] = m[7];
    #pragma unroll
    for (int j = 1; j < 8; ++j) { q[j] = 0.f; s[j] = 0.f; }
    const float T[7][8] = {
        { 0.f, 1.f, 0.f,  0.f, 0.f, 0.f, 0.f, 0.f},   // t1
        {-2.f, 0.f, 1.f,  0.f, 0.f, 0.f, 0.f, 0.f},   // t2
        { 0.f,-3.f, 0.f,  1.f, 0.f, 0.f, 0.f, 0.f},   // t3
        { 2.f, 0.f,-4.f,  0.f, 1.f, 0.f, 0.f, 0.f},   // t4
        { 0.f, 5.f, 0.f, -5.f, 0.f, 1.f, 0.f, 0.f},   // t5
        {-2.f, 0.f, 9.f,  0.f,-6.f, 0.f, 1.f, 0.f},   // t6
        { 0.f,-7.f, 0.f, 14.f, 0.f,-7.f, 0.f, 1.f}};  // t7
    #pragma unroll
    for (int t = 1; t <= 7; ++t)
        #pragma unroll
        for (int j = 0; j < 8; ++j) {
            q[j] = fmaf(p[7 + t], T[t - 1][j], q[j]);
            s[j] = fmaf(m[7 + t], T[t - 1][j], s[j]);
        }
    #pragma unroll
    for (int j = 0; j < 8; ++j) {
        gC[j]     = pk2(q[j], q[j]);
        gC[8 + j] = pk2(s[j], s[j]);
    }
    gK2 = 2.0f * (cb[1] - cb[0]) * invT * 1.4426950408889634f;
    gPres = pp[0];
}

// ---------------- main kernel: flat, one tile (64 quads) per warp -----------
__global__ __launch_bounds__(256, 4) void ThermoQuantizer_50122268345057_kernel(
    const float* __restrict__ x,
    float* __restrict__ out,
    int n4)
{
    __shared__ ull sC[16];
    __shared__ float sK2, sPres;

    const int tid = threadIdx.x;
    if (tid < 16) {
        sC[tid] = gC[tid];
        if (tid == 0) { sK2 = gK2; sPres = gPres; }
    }
    __syncthreads();

    const int lane = tid & 31;
    const int h = lane >> 4;            // which of the warp's 2 groups
    const int ql = lane & 15;
    const int tile = blockIdx.x * 8 + (tid >> 5);
    const int qb = tile * 64 + h * 32 + ql;
    if (qb + 16 > n4) return;           // groups are whole-or-absent; warp-uniform

    const float4* __restrict__ x4 = reinterpret_cast<const float4*>(x);
    const float4 a0 = x4[qb];
    const float4 a1 = x4[qb + 16];

    // ---- group abs-mean over this 16-lane half (128 elements) ----
    float ss = (fabsf(a0.x) + fabsf(a0.y)) + (fabsf(a0.z) + fabsf(a0.w))
             + (fabsf(a1.x) + fabsf(a1.y)) + (fabsf(a1.z) + fabsf(a1.w));
    ss += __shfl_xor_sync(FULL_MASK, ss, 8);
    ss += __shfl_xor_sync(FULL_MASK, ss, 4);
    ss += __shfl_xor_sync(FULL_MASK, ss, 2);
    ss += __shfl_xor_sync(FULL_MASK, ss, 1);
    const float mean_c = fmaxf(ss * (1.0f / 128.0f), 1e-5f);
    const float kk = sK2 * rcpf(mean_c);
    const ull kk2 = pk2(kk, kk);
    const float pm = sPres * mean_c;
    const ull pm2 = pk2(pm, pm);
    const float onemp = 1.0f - sPres;
    const ull om2 = pk2(onemp, onemp);

    ull xp[4] = { pk2(a0.x, a0.y), pk2(a0.z, a0.w),
                  pk2(a1.x, a1.y), pk2(a1.z, a1.w) };

    // ---- per-pair: R = 2^clamp(x*kk, +-10), z = R + 1/R ----
    // clamp engages only where the softmax is already pinned to an end code.
    ull RP[4], zP[4], accQ[4], accS[4];
    const ull cq7 = sC[7], cs7 = sC[15];
    #pragma unroll
    for (int pI = 0; pI < 4; ++pI) {
        ull aP = mul2(xp[pI], kk2);
        float alo, ahi; upk2(aP, alo, ahi);
        alo = fminf(fmaxf(alo, -10.0f), 10.0f);
        ahi = fminf(fmaxf(ahi, -10.0f), 10.0f);
        float r0 = ex2f(alo), r1 = ex2f(ahi);
        float i0 = rcpf(r0),  i1 = rcpf(r1);
        RP[pI] = pk2(r0, r1);
        zP[pI] = add2(RP[pI], pk2(i0, i1));
        accQ[pI] = cq7; accS[pI] = cs7;
    }

    // ---- dual degree-7 Horner, 8 independent packed chains ----
    #pragma unroll
    for (int j = 6; j >= 0; --j) {
        const ull cq = sC[j], cs = sC[8 + j];
        #pragma unroll
        for (int pI = 0; pI < 4; ++pI) {
            accQ[pI] = fma2(accQ[pI], zP[pI], cq);
            accS[pI] = fma2(accS[pI], zP[pI], cs);
        }
    }

    // ---- qxn = (R-1)S / ((R+1)Q);  out = (1-p)x + p*mean*qxn ----
    const ull ONE2  = pk2(1.0f, 1.0f);
    const ull MONE2 = pk2(-1.0f, -1.0f);
    float resv[8];
    #pragma unroll
    for (int pI = 0; pI < 4; ++pI) {
        ull vP = mul2(accQ[pI], add2(RP[pI], ONE2));
        ull uP = mul2(accS[pI], add2(RP[pI], MONE2));
        float v0, v1; upk2(vP, v0, v1);
        ull rP = pk2(rcpf(v0), rcpf(v1));
        ull qP = mul2(uP, rP);
        ull resP = fma2(pm2, qP, mul2(om2, xp[pI]));
        upk2(resP, resv[2 * pI], resv[2 * pI + 1]);
    }

    float4* __restrict__ o4 = reinterpret_cast<float4*>(out);
    o4[qb]      = make_float4(resv[0], resv[1], resv[2], resv[3]);
    o4[qb + 16] = make_float4(resv[4], resv[5], resv[6], resv[7]);
}

extern "C" void kernel_launch(void* const* d_in, const int* in_sizes, int n_in,
                              void* d_out, int out_size) {
    const float* x  = (const float*)d_in[0];
    const float* cbk = (const float*)d_in[1];
    const float* pr = (const float*)d_in[2];
    const float* tp = (const float*)d_in[3];
    float* out = (float*)d_out;

    tq_setup_kernel<<<1, 32>>>(cbk, pr, tp);

    const int n4 = out_size / 4;                    // float4 quads
    const int quadsPerBlock = 8 * 64;               // 8 warps * 64 quads
    const int blocks = (n4 + quadsPerBlock - 1) / quadsPerBlock;
    ThermoQuantizer_50122268345057_kernel<<<blocks, 256>>>(x, out, n4);
}

// round 5
// speedup vs baseline: 1.2797x; 1.1273x over previous
#include <cuda_runtime.h>
#include <cuda_bf16.h>

// ThermoQuantizer: groupwise abs-mean scale + softmax quantization onto a
// uniform 16-level codebook + lerp.
//
// Math: p_k ∝ G_k R^k, R = 2^(xn*K2), K2 = 2D/T*log2(e), G_k = exp(-c_k^2/T).
// Symmetric codebook => den(R) palindromic / num(R) anti-palindromic (deg 15):
//   den = (R+1) R^7 Q(z),  num = (R-1) R^7 S(z),  z = R + 1/R,  Q,S deg 7.
//   qxn = (R-1)S(z) / ((R+1)Q(z))   -- 7 packed FMA + 3 MUFU per element.
//
// Single persistent kernel, one resident wave (152 SM x 4 blocks x 256 thr).
// Q,S coefficients derived per block by warp 0 in ~300 cycles via lane-parallel
// shfl-scan (synthetic division = prefix sums) + per-lane basis transform.
// 1 warp = 2 groups (half-warp per group), 8 elems/thread, all math in f32x2.

typedef unsigned long long ull;
#define FULL_MASK 0xFFFFFFFFu

// Basis-transform columns: row j (0..7) holds T[t][j] for t=1..7, where
// t_t(z) = R^t + R^-t expanded in powers of z.
__device__ const float gTcol[56] = {
    0.f,-2.f, 0.f,  2.f, 0.f,-2.f, 0.f,   // j=0
    1.f, 0.f,-3.f,  0.f, 5.f, 0.f,-7.f,   // j=1
    0.f, 1.f, 0.f, -4.f, 0.f, 9.f, 0.f,   // j=2
    0.f, 0.f, 1.f,  0.f,-5.f, 0.f,14.f,   // j=3
    0.f, 0.f, 0.f,  1.f, 0.f,-6.f, 0.f,   // j=4
    0.f, 0.f, 0.f,  0.f, 1.f, 0.f,-7.f,   // j=5
    0.f, 0.f, 0.f,  0.f, 0.f, 1.f, 0.f,   // j=6
    0.f, 0.f, 0.f,  0.f, 0.f, 0.f, 1.f};  // j=7

__device__ __forceinline__ ull pk2(float lo, float hi) {
    ull r; asm("mov.b64 %0, {%1, %2};" : "=l"(r) : "f"(lo), "f"(hi)); return r;
}
__device__ __forceinline__ void upk2(ull v, float& lo, float& hi) {
    asm("mov.b64 {%0, %1}, %2;" : "=f"(lo), "=f"(hi) : "l"(v));
}
__device__ __forceinline__ ull fma2(ull a, ull b, ull c) {
    ull d; asm("fma.rn.f32x2 %0, %1, %2, %3;" : "=l"(d) : "l"(a), "l"(b), "l"(c)); return d;
}
__device__ __forceinline__ ull mul2(ull a, ull b) {
    ull d; asm("mul.rn.f32x2 %0, %1, %2;" : "=l"(d) : "l"(a), "l"(b)); return d;
}
__device__ __forceinline__ ull add2(ull a, ull b) {
    ull d; asm("add.rn.f32x2 %0, %1, %2;" : "=l"(d) : "l"(a), "l"(b)); return d;
}
__device__ __forceinline__ float ex2f(float a) {
    float r; asm("ex2.approx.ftz.f32 %0, %1;" : "=f"(r) : "f"(a)); return r;
}
__device__ __forceinline__ float rcpf(float a) {
    float r; asm("rcp.approx.ftz.f32 %0, %1;" : "=f"(r) : "f"(a)); return r;
}

__global__ __launch_bounds__(256, 4) void ThermoQuantizer_50122268345057_kernel(
    const float* __restrict__ x,
    const float* __restrict__ cb,
    const float* __restrict__ pp,
    const float* __restrict__ pt,
    float* __restrict__ out,
    int n4)
{
    __shared__ ull sC[16];            // (q_j,q_j) j=0..7 then (s_j,s_j)
    __shared__ float sK2, sPres;

    const int tid = threadIdx.x;

    // ---- per-block coefficient derivation (warp 0, lane-parallel) ----
    if (tid < 32) {
        const int lane = tid;
        const int k = lane & 15;
        const float invT = 1.0f / (pt[0] + 1e-6f);
        const float c = cb[k];
        const float g = __expf(-c * c * invT);
        const float Hk = g * c;

        // p[j] = (-1)^j * prefixsum((-1)^i G_i);  m[j] = -prefixsum(H_i)
        float sg = (k & 1) ? -g : g;
        float sh = Hk;
        #pragma unroll
        for (int o = 1; o <= 8; o <<= 1) {
            float tg = __shfl_up_sync(FULL_MASK, sg, o);
            float th = __shfl_up_sync(FULL_MASK, sh, o);
            if (lane >= o) { sg += tg; sh += th; }
        }
        const float pv = (k & 1) ? -sg : sg;
        const float mv = -sh;

        // broadcast p[7..14], m[7..14]
        float pb[8], mb[8];
        #pragma unroll
        for (int t = 0; t < 8; ++t) {
            pb[t] = __shfl_sync(FULL_MASK, pv, 7 + t);
            mb[t] = __shfl_sync(FULL_MASK, mv, 7 + t);
        }

        if (lane < 8) {
            float q = (lane == 0) ? pb[0] : 0.f;
            float s = (lane == 0) ? mb[0] : 0.f;
            const float* Tc = &gTcol[lane * 7];
            #pragma unroll
            for (int t = 1; t <= 7; ++t) {
                float tc = Tc[t - 1];
                q = fmaf(pb[t], tc, q);
                s = fmaf(mb[t], tc, s);
            }
            sC[lane]     = pk2(q, q);
            sC[lane + 8] = pk2(s, s);
        }
        if (lane == 0) {
            sK2 = 2.0f * (cb[1] - cb[0]) * invT * 1.4426950408889634f;
            sPres = pp[0];
        }
    }
    __syncthreads();

    // ---- persistent tile loop: 1 warp = 1 tile of 64 quads (2 groups) ----
    const int lane = tid & 31;
    const int h = lane >> 4;
    const int ql = lane & 15;
    const int warpsTotal = gridDim.x * 8;
    const int wId = blockIdx.x * 8 + (tid >> 5);
    const int numTiles = (n4 + 63) >> 6;

    const float K2 = sK2, pres = sPres;
    const float onemp = 1.0f - pres;
    const ull om2  = pk2(onemp, onemp);
    const ull ONE2 = pk2(1.0f, 1.0f);
    const ull MONE2 = pk2(-1.0f, -1.0f);

    const float4* __restrict__ x4 = reinterpret_cast<const float4*>(x);
    float4* __restrict__ o4 = reinterpret_cast<float4*>(out);

    for (int tile = wId; tile < numTiles; tile += warpsTotal) {
        const int qb = tile * 64 + h * 32 + ql;
        const bool vld = (qb + 16) <= n4;      // group whole-or-absent
        float4 a0, a1;
        if (vld) { a0 = x4[qb]; a1 = x4[qb + 16]; }
        else     { a0 = make_float4(0.f,0.f,0.f,0.f); a1 = a0; }

        // group abs-mean over this 16-lane half (128 elements)
        float ss = (fabsf(a0.x) + fabsf(a0.y)) + (fabsf(a0.z) + fabsf(a0.w))
                 + (fabsf(a1.x) + fabsf(a1.y)) + (fabsf(a1.z) + fabsf(a1.w));
        ss += __shfl_xor_sync(FULL_MASK, ss, 8);
        ss += __shfl_xor_sync(FULL_MASK, ss, 4);
        ss += __shfl_xor_sync(FULL_MASK, ss, 2);
        ss += __shfl_xor_sync(FULL_MASK, ss, 1);
        const float mean_c = fmaxf(ss * (1.0f / 128.0f), 1e-5f);
        const float kk = K2 * rcpf(mean_c);
        const ull kk2 = pk2(kk, kk);
        const float pm = pres * mean_c;
        const ull pm2 = pk2(pm, pm);

        ull xp[4] = { pk2(a0.x, a0.y), pk2(a0.z, a0.w),
                      pk2(a1.x, a1.y), pk2(a1.z, a1.w) };

        // R = 2^clamp(x*kk, +-10), z = R + 1/R
        // (clamp engages only where the softmax is already pinned to an end code)
        ull RP[4], zP[4], accQ[4], accS[4];
        const ull cq7 = sC[7], cs7 = sC[15];
        #pragma unroll
        for (int pI = 0; pI < 4; ++pI) {
            ull aP = mul2(xp[pI], kk2);
            float alo, ahi; upk2(aP, alo, ahi);
            alo = fminf(fmaxf(alo, -10.0f), 10.0f);
            ahi = fminf(fmaxf(ahi, -10.0f), 10.0f);
            float r0 = ex2f(alo), r1 = ex2f(ahi);
            float i0 = rcpf(r0),  i1 = rcpf(r1);
            RP[pI] = pk2(r0, r1);
            zP[pI] = add2(RP[pI], pk2(i0, i1));
            accQ[pI] = cq7; accS[pI] = cs7;
        }

        // dual degree-7 Horner, 8 independent packed chains
        #pragma unroll
        for (int j = 6; j >= 0; --j) {
            const ull cq = sC[j], cs = sC[8 + j];
            #pragma unroll
            for (int pI = 0; pI < 4; ++pI) {
                accQ[pI] = fma2(accQ[pI], zP[pI], cq);
                accS[pI] = fma2(accS[pI], zP[pI], cs);
            }
        }

        // qxn = (R-1)S / ((R+1)Q);  out = (1-p)x + p*mean*qxn
        float resv[8];
        #pragma unroll
        for (int pI = 0; pI < 4; ++pI) {
            ull vP = mul2(accQ[pI], add2(RP[pI], ONE2));
            ull uP = mul2(accS[pI], add2(RP[pI], MONE2));
            float v0, v1; upk2(vP, v0, v1);
            ull rP = pk2(rcpf(v0), rcpf(v1));
            ull qP = mul2(uP, rP);
            ull resP = fma2(pm2, qP, mul2(om2, xp[pI]));
            upk2(resP, resv[2 * pI], resv[2 * pI + 1]);
        }

        if (vld) {
            o4[qb]      = make_float4(resv[0], resv[1], resv[2], resv[3]);
            o4[qb + 16] = make_float4(resv[4], resv[5], resv[6], resv[7]);
        }
    }
}

extern "C" void kernel_launch(void* const* d_in, const int* in_sizes, int n_in,
                              void* d_out, int out_size) {
    const float* x  = (const float*)d_in[0];
    const float* cbk = (const float*)d_in[1];
    const float* pr = (const float*)d_in[2];
    const float* tp = (const float*)d_in[3];
    float* out = (float*)d_out;

    const int n4 = out_size / 4;               // float4 quads
    const int numTiles = (n4 + 63) >> 6;
    int blocks = 152 * 4;                      // exactly one resident wave
    const int maxBlocks = (numTiles + 7) / 8;  // 8 warps/block
    if (blocks > maxBlocks) blocks = maxBlocks;
    if (blocks < 1) blocks = 1;
    ThermoQuantizer_50122268345057_kernel<<<blocks, 256>>>(x, cbk, pr, tp, out, n4);
}

// round 6
// speedup vs baseline: 1.3868x; 1.0837x over previous
#include <cuda_runtime.h>
#include <cuda_bf16.h>

// ThermoQuantizer: groupwise abs-mean scale + softmax quantization onto a
// uniform 16-level codebook + lerp.
//
// Math: p_k ∝ G_k R^k, R = 2^(xn*K2), K2 = 2D/T*log2(e), G_k = exp(-c_k^2/T).
// Symmetric codebook => den(R) palindromic / num(R) anti-palindromic (deg 15):
//   den = (R+1) R^7 Q(z),  num = (R-1) R^7 S(z),  z = R + 1/R,  Q,S deg 7.
//   qxn = (R-1)S(z) / ((R+1)Q(z))   -- 7 packed FMA + 3 MUFU per element.
//
// Single persistent kernel, one resident wave (152 SM x 5 blocks x 256 thr).
// launch_bounds(256,5) caps regs at 51 -> 40 warps/SM for latency coverage;
// ptxas re-reads Horner coefficients from shared just-in-time instead of
// caching all 16 in registers. Q,S coefficients derived per block by warp 0
// via lane-parallel shfl-scan. 1 warp = 2 groups, 8 elems/thread, f32x2 math.

typedef unsigned long long ull;
#define FULL_MASK 0xFFFFFFFFu

// Basis-transform columns: row j (0..7) holds T[t][j] for t=1..7, where
// t_t(z) = R^t + R^-t expanded in powers of z.
__device__ const float gTcol[56] = {
    0.f,-2.f, 0.f,  2.f, 0.f,-2.f, 0.f,   // j=0
    1.f, 0.f,-3.f,  0.f, 5.f, 0.f,-7.f,   // j=1
    0.f, 1.f, 0.f, -4.f, 0.f, 9.f, 0.f,   // j=2
    0.f, 0.f, 1.f,  0.f,-5.f, 0.f,14.f,   // j=3
    0.f, 0.f, 0.f,  1.f, 0.f,-6.f, 0.f,   // j=4
    0.f, 0.f, 0.f,  0.f, 1.f, 0.f,-7.f,   // j=5
    0.f, 0.f, 0.f,  0.f, 0.f, 1.f, 0.f,   // j=6
    0.f, 0.f, 0.f,  0.f, 0.f, 0.f, 1.f};  // j=7

__device__ __forceinline__ ull pk2(float lo, float hi) {
    ull r; asm("mov.b64 %0, {%1, %2};" : "=l"(r) : "f"(lo), "f"(hi)); return r;
}
__device__ __forceinline__ void upk2(ull v, float& lo, float& hi) {
    asm("mov.b64 {%0, %1}, %2;" : "=f"(lo), "=f"(hi) : "l"(v));
}
__device__ __forceinline__ ull fma2(ull a, ull b, ull c) {
    ull d; asm("fma.rn.f32x2 %0, %1, %2, %3;" : "=l"(d) : "l"(a), "l"(b), "l"(c)); return d;
}
__device__ __forceinline__ ull mul2(ull a, ull b) {
    ull d; asm("mul.rn.f32x2 %0, %1, %2;" : "=l"(d) : "l"(a), "l"(b)); return d;
}
__device__ __forceinline__ ull add2(ull a, ull b) {
    ull d; asm("add.rn.f32x2 %0, %1, %2;" : "=l"(d) : "l"(a), "l"(b)); return d;
}
__device__ __forceinline__ float ex2f(float a) {
    float r; asm("ex2.approx.ftz.f32 %0, %1;" : "=f"(r) : "f"(a)); return r;
}
__device__ __forceinline__ float rcpf(float a) {
    float r; asm("rcp.approx.ftz.f32 %0, %1;" : "=f"(r) : "f"(a)); return r;
}

__global__ __launch_bounds__(256, 5) void ThermoQuantizer_50122268345057_kernel(
    const float* __restrict__ x,
    const float* __restrict__ cb,
    const float* __restrict__ pp,
    const float* __restrict__ pt,
    float* __restrict__ out,
    int n4)
{
    __shared__ ull sC[16];            // (q_j,q_j) j=0..7 then (s_j,s_j)
    __shared__ float sK2, sPres;

    const int tid = threadIdx.x;

    // ---- per-block coefficient derivation (warp 0, lane-parallel) ----
    if (tid < 32) {
        const int lane = tid;
        const int k = lane & 15;
        const float invT = 1.0f / (pt[0] + 1e-6f);
        const float c = cb[k];
        const float g = __expf(-c * c * invT);
        const float Hk = g * c;

        // p[j] = (-1)^j * prefixsum((-1)^i G_i);  m[j] = -prefixsum(H_i)
        float sg = (k & 1) ? -g : g;
        float sh = Hk;
        #pragma unroll
        for (int o = 1; o <= 8; o <<= 1) {
            float tg = __shfl_up_sync(FULL_MASK, sg, o);
            float th = __shfl_up_sync(FULL_MASK, sh, o);
            if (lane >= o) { sg += tg; sh += th; }
        }
        const float pv = (k & 1) ? -sg : sg;
        const float mv = -sh;

        // broadcast p[7..14], m[7..14]
        float pb[8], mb[8];
        #pragma unroll
        for (int t = 0; t < 8; ++t) {
            pb[t] = __shfl_sync(FULL_MASK, pv, 7 + t);
            mb[t] = __shfl_sync(FULL_MASK, mv, 7 + t);
        }

        if (lane < 8) {
            float q = (lane == 0) ? pb[0] : 0.f;
            float s = (lane == 0) ? mb[0] : 0.f;
            const float* Tc = &gTcol[lane * 7];
            #pragma unroll
            for (int t = 1; t <= 7; ++t) {
                float tc = Tc[t - 1];
                q = fmaf(pb[t], tc, q);
                s = fmaf(mb[t], tc, s);
            }
            sC[lane]     = pk2(q, q);
            sC[lane + 8] = pk2(s, s);
        }
        if (lane == 0) {
            sK2 = 2.0f * (cb[1] - cb[0]) * invT * 1.4426950408889634f;
            sPres = pp[0];
        }
    }
    __syncthreads();

    // ---- persistent tile loop: 1 warp = 1 tile of 64 quads (2 groups) ----
    const int lane = tid & 31;
    const int h = lane >> 4;
    const int ql = lane & 15;
    const int warpsTotal = gridDim.x * 8;
    const int wId = blockIdx.x * 8 + (tid >> 5);
    const int numTiles = (n4 + 63) >> 6;

    const float K2 = sK2, pres = sPres;
    const float onemp = 1.0f - pres;
    const ull om2  = pk2(onemp, onemp);
    const ull ONE2 = pk2(1.0f, 1.0f);
    const ull MONE2 = pk2(-1.0f, -1.0f);

    const float4* __restrict__ x4 = reinterpret_cast<const float4*>(x);
    float4* __restrict__ o4 = reinterpret_cast<float4*>(out);

    for (int tile = wId; tile < numTiles; tile += warpsTotal) {
        const int qb = tile * 64 + h * 32 + ql;
        const bool vld = (qb + 16) <= n4;      // group whole-or-absent
        float4 a0, a1;
        if (vld) { a0 = x4[qb]; a1 = x4[qb + 16]; }
        else     { a0 = make_float4(0.f,0.f,0.f,0.f); a1 = a0; }

        // group abs-mean over this 16-lane half (128 elements)
        float ss = (fabsf(a0.x) + fabsf(a0.y)) + (fabsf(a0.z) + fabsf(a0.w))
                 + (fabsf(a1.x) + fabsf(a1.y)) + (fabsf(a1.z) + fabsf(a1.w));
        ss += __shfl_xor_sync(FULL_MASK, ss, 8);
        ss += __shfl_xor_sync(FULL_MASK, ss, 4);
        ss += __shfl_xor_sync(FULL_MASK, ss, 2);
        ss += __shfl_xor_sync(FULL_MASK, ss, 1);
        const float mean_c = fmaxf(ss * (1.0f / 128.0f), 1e-5f);
        const float kk = K2 * rcpf(mean_c);
        const ull kk2 = pk2(kk, kk);
        const float pm = pres * mean_c;
        const ull pm2 = pk2(pm, pm);

        ull xp[4] = { pk2(a0.x, a0.y), pk2(a0.z, a0.w),
                      pk2(a1.x, a1.y), pk2(a1.z, a1.w) };

        // R = 2^clamp(x*kk, +-10), z = R + 1/R
        // (clamp engages only where the softmax is already pinned to an end code)
        ull RP[4], zP[4], accQ[4], accS[4];
        const ull cq7 = sC[7], cs7 = sC[15];
        #pragma unroll
        for (int pI = 0; pI < 4; ++pI) {
            ull aP = mul2(xp[pI], kk2);
            float alo, ahi; upk2(aP, alo, ahi);
            alo = fminf(fmaxf(alo, -10.0f), 10.0f);
            ahi = fminf(fmaxf(ahi, -10.0f), 10.0f);
            float r0 = ex2f(alo), r1 = ex2f(ahi);
            float i0 = rcpf(r0),  i1 = rcpf(r1);
            RP[pI] = pk2(r0, r1);
            zP[pI] = add2(RP[pI], pk2(i0, i1));
            accQ[pI] = cq7; accS[pI] = cs7;
        }

        // dual degree-7 Horner, 8 independent packed chains
        #pragma unroll
        for (int j = 6; j >= 0; --j) {
            const ull cq = sC[j], cs = sC[8 + j];
            #pragma unroll
            for (int pI = 0; pI < 4; ++pI) {
                accQ[pI] = fma2(accQ[pI], zP[pI], cq);
                accS[pI] = fma2(accS[pI], zP[pI], cs);
            }
        }

        // qxn = (R-1)S / ((R+1)Q);  out = (1-p)x + p*mean*qxn
        float resv[8];
        #pragma unroll
        for (int pI = 0; pI < 4; ++pI) {
            ull vP = mul2(accQ[pI], add2(RP[pI], ONE2));
            ull uP = mul2(accS[pI], add2(RP[pI], MONE2));
            float v0, v1; upk2(vP, v0, v1);
            ull rP = pk2(rcpf(v0), rcpf(v1));
            ull qP = mul2(uP, rP);
            ull resP = fma2(pm2, qP, mul2(om2, xp[pI]));
            upk2(resP, resv[2 * pI], resv[2 * pI + 1]);
        }

        if (vld) {
            o4[qb]      = make_float4(resv[0], resv[1], resv[2], resv[3]);
            o4[qb + 16] = make_float4(resv[4], resv[5], resv[6], resv[7]);
        }
    }
}

extern "C" void kernel_launch(void* const* d_in, const int* in_sizes, int n_in,
                              void* d_out, int out_size) {
    const float* x  = (const float*)d_in[0];
    const float* cbk = (const float*)d_in[1];
    const float* pr = (const float*)d_in[2];
    const float* tp = (const float*)d_in[3];
    float* out = (float*)d_out;

    const int n4 = out_size / 4;               // float4 quads
    const int numTiles = (n4 + 63) >> 6;
    int blocks = 152 * 5;                      // one resident wave at 5 blocks/SM
    const int maxBlocks = (numTiles + 7) / 8;  // 8 warps/block
    if (blocks > maxBlocks) blocks = maxBlocks;
    if (blocks < 1) blocks = 1;
    ThermoQuantizer_50122268345057_kernel<<<blocks, 256>>>(x, cbk, pr, tp, out, n4);
}